// round 1
// baseline (speedup 1.0000x reference)
#include <cuda_runtime.h>

// GNN_21474836480432 — 3-layer GNN forward on GB300 (sm_103a)
// out = mean over layers of ego, where per layer:
//   agg = segment_sum(vals * ego[cols], rows);  ego = agg + agg*ego
//
// Strategy: everything is L2-resident (ego/agg = 19.2MB each << 126MB L2).
// SpMM via vectorized L2 atomics (red.global.add.v4.f32), 24 float4 lanes
// per edge so gathers coalesce. Combine kernel fuses gating, accumulation,
// final scaling, and zeroing agg for the next layer.

#define N_NODES 50000
#define EMB     96
#define CHUNKS  24                      // EMB / 4 (float4 chunks per row)
#define NVEC    (N_NODES * CHUNKS)      // 1,200,000 float4

__device__ __align__(16) float4 g_ego[NVEC];
__device__ __align__(16) float4 g_agg[NVEC];
__device__ int g_idx64;                 // 1 if rows/cols are int64, 0 if int32

// --- dtype detection: int64 indices < 2^31 have all-zero high 32-bit words ---
__global__ void reset_flag_kernel() { g_idx64 = 1; }

__global__ void detect_i64_kernel(const unsigned int* __restrict__ raw, int half_n) {
    int i = blockIdx.x * blockDim.x + threadIdx.x;
    int stride = gridDim.x * blockDim.x;
    for (; i < half_n; i += stride) {
        // safe for both dtypes: index 2*i+1 <= n_elems-1 when i < n_elems/2
        if (raw[2 * i + 1] != 0u) g_idx64 = 0;   // racing stores of 0 are fine
    }
}

// --- init: ego = X, acc = X, agg = 0 ---
__global__ void init_kernel(const float4* __restrict__ X, float4* __restrict__ acc) {
    int i = blockIdx.x * blockDim.x + threadIdx.x;
    if (i < NVEC) {
        float4 x = X[i];
        g_ego[i] = x;
        acc[i]   = x;
        g_agg[i] = make_float4(0.f, 0.f, 0.f, 0.f);
    }
}

// --- SpMM: agg[rows[e]] += vals[e] * ego[cols[e]]  (vector red to L2) ---
__global__ void spmm_kernel(const float* __restrict__ vals,
                            const void*  __restrict__ rows,
                            const void*  __restrict__ cols,
                            int E) {
    int e = blockIdx.x * blockDim.y + threadIdx.y;
    if (e >= E) return;
    int tx = threadIdx.x;                // 0..23 feature chunk

    long long r, c;
    if (g_idx64) {
        r = ((const long long*)rows)[e];
        c = ((const long long*)cols)[e];
    } else {
        r = (long long)((const int*)rows)[e];
        c = (long long)((const int*)cols)[e];
    }
    float v = __ldg(vals + e);

    float4 x = g_ego[c * CHUNKS + tx];   // coalesced 384B row gather
    float4* dst = &g_agg[r * CHUNKS + tx];
    asm volatile("red.global.add.v4.f32 [%0], {%1, %2, %3, %4};"
                 :: "l"(dst), "f"(v * x.x), "f"(v * x.y),
                    "f"(v * x.z), "f"(v * x.w)
                 : "memory");
}

// --- combine: ego = agg + agg*ego; acc = (acc + ego)*scale; agg = 0 ---
__global__ void combine_kernel(float4* __restrict__ acc, float scale) {
    int i = blockIdx.x * blockDim.x + threadIdx.x;
    if (i < NVEC) {
        float4 a = g_agg[i];
        float4 e = g_ego[i];
        float4 en = make_float4(fmaf(a.x, e.x, a.x),
                                fmaf(a.y, e.y, a.y),
                                fmaf(a.z, e.z, a.z),
                                fmaf(a.w, e.w, a.w));
        g_ego[i] = en;
        float4 o = acc[i];
        o = make_float4((o.x + en.x) * scale,
                        (o.y + en.y) * scale,
                        (o.z + en.z) * scale,
                        (o.w + en.w) * scale);
        acc[i] = o;
        g_agg[i] = make_float4(0.f, 0.f, 0.f, 0.f);   // pre-zero for next layer
    }
}

extern "C" void kernel_launch(void* const* d_in, const int* in_sizes, int n_in,
                              void* d_out, int out_size) {
    const float4* X    = (const float4*)d_in[0];   // [N, 96] f32
    const float*  vals = (const float*) d_in[1];   // [E] f32
    const void*   rows = d_in[2];                  // [E] int64 or int32
    const void*   cols = d_in[3];                  // [E] int64 or int32
    int E = in_sizes[1];
    float4* acc = (float4*)d_out;                  // [N, 96] f32

    // dtype detection (deterministic, capture-safe)
    reset_flag_kernel<<<1, 1>>>();
    detect_i64_kernel<<<512, 256>>>((const unsigned int*)rows, E / 2);

    // init ego/acc/agg
    init_kernel<<<(NVEC + 255) / 256, 256>>>(X, acc);

    dim3 spmm_block(CHUNKS, 8);                    // 192 threads, 8 edges/block
    int  spmm_grid = (E + 7) / 8;
    int  comb_grid = (NVEC + 255) / 256;

    for (int layer = 0; layer < 3; layer++) {
        spmm_kernel<<<spmm_grid, spmm_block>>>(vals, rows, cols, E);
        float scale = (layer == 2) ? 0.25f : 1.0f;
        combine_kernel<<<comb_grid, 256>>>(acc, scale);
    }
}

// round 3
// speedup vs baseline: 1.6124x; 1.6124x over previous
#include <cuda_runtime.h>

// GNN_21474836480432 — 3-layer GNN forward, CSR + fused-epilogue version.
// Per layer: agg = segsum(vals * ego[cols], rows); ego = agg + agg*ego; acc += ego.
// CSR built in-launch (hist/scan/scatter), SpMM accumulates each output row in
// registers (24 threads x float4 per row) -> no fp atomics, gating/acc fused.

#define N_NODES 50000
#define N_EDGES_MAX 800000
#define EMB     96
#define CHUNKS  24                      // EMB/4
#define NVEC    (N_NODES * CHUNKS)

__device__ __align__(16) float4 g_egoA[NVEC];
__device__ __align__(16) float4 g_egoB[NVEC];
__device__ int  g_deg[N_NODES];
__device__ int  g_off[N_NODES + 1];
__device__ int  g_cursor[N_NODES];
__device__ __align__(8) int2 g_colval[N_EDGES_MAX];   // (col, float_bits(val))
__device__ int  g_idx64;

// ---------- dtype detection: int64 indices < 2^31 => high words all zero ----
__global__ void reset_flag_kernel() { g_idx64 = 1; }

__global__ void detect_i64_kernel(const unsigned int* __restrict__ raw, int half_n) {
    int i = blockIdx.x * blockDim.x + threadIdx.x;
    int stride = gridDim.x * blockDim.x;
    for (; i < half_n; i += stride)
        if (raw[2 * i + 1] != 0u) g_idx64 = 0;
}

// ---------- CSR build --------------------------------------------------------
__global__ void zero_deg_kernel() {
    int i = blockIdx.x * blockDim.x + threadIdx.x;
    if (i < N_NODES) g_deg[i] = 0;
}

__global__ void hist_kernel(const void* __restrict__ rows, int E) {
    int e = blockIdx.x * blockDim.x + threadIdx.x;
    if (e >= E) return;
    int r = g_idx64 ? (int)((const long long*)rows)[e]
                    : ((const int*)rows)[e];
    atomicAdd(&g_deg[r], 1);
}

// single-block exclusive scan over g_deg -> g_off, g_cursor (1024 threads)
__global__ void scan_kernel() {
    __shared__ int wsum[32];
    __shared__ int s_carry;
    int tid = threadIdx.x;
    int lane = tid & 31, wid = tid >> 5;
    if (tid == 0) s_carry = 0;
    __syncthreads();
    for (int base = 0; base < N_NODES; base += 1024) {
        int i = base + tid;
        int v = (i < N_NODES) ? g_deg[i] : 0;
        int incl = v;
        #pragma unroll
        for (int d = 1; d < 32; d <<= 1) {
            int t = __shfl_up_sync(0xffffffffu, incl, d);
            if (lane >= d) incl += t;
        }
        if (lane == 31) wsum[wid] = incl;
        __syncthreads();
        if (wid == 0) {
            int w = wsum[lane];
            int wincl = w;
            #pragma unroll
            for (int d = 1; d < 32; d <<= 1) {
                int t = __shfl_up_sync(0xffffffffu, wincl, d);
                if (lane >= d) wincl += t;
            }
            wsum[lane] = wincl - w;   // exclusive among warps
        }
        __syncthreads();
        int excl = incl - v + wsum[wid] + s_carry;
        if (i < N_NODES) { g_off[i] = excl; g_cursor[i] = excl; }
        __syncthreads();
        if (tid == 1023) s_carry = excl + v;
        __syncthreads();
    }
    if (tid == 0) g_off[N_NODES] = s_carry;
}

__global__ void scatter_kernel(const float* __restrict__ vals,
                               const void* __restrict__ rows,
                               const void* __restrict__ cols, int E) {
    int e = blockIdx.x * blockDim.x + threadIdx.x;
    if (e >= E) return;
    int r, c;
    if (g_idx64) {
        r = (int)((const long long*)rows)[e];
        c = (int)((const long long*)cols)[e];
    } else {
        r = ((const int*)rows)[e];
        c = ((const int*)cols)[e];
    }
    int p = atomicAdd(&g_cursor[r], 1);
    g_colval[p] = make_int2(c, __float_as_int(__ldg(vals + e)));
}

// ---------- fused layer: SpMM (register agg) + gating + acc update ----------
// mode 0: first layer  (src == X; acc = X + ego_new)
// mode 1: middle layer (acc += ego_new)
// mode 2: last layer   (acc = (acc + ego_new) * 0.25; dst not written)
__global__ void __launch_bounds__(192)
gnn_layer_kernel(const float4* __restrict__ src,
                 float4* __restrict__ dst,
                 float4* __restrict__ acc,
                 int mode) {
    int row = blockIdx.x * blockDim.y + threadIdx.y;
    if (row >= N_NODES) return;
    int tx = threadIdx.x;                  // 0..23

    int start = g_off[row];
    int end   = g_off[row + 1];

    float4 a = make_float4(0.f, 0.f, 0.f, 0.f);
    int e = start;
    for (; e + 2 <= end; e += 2) {
        int2 cv0 = g_colval[e];
        int2 cv1 = g_colval[e + 1];
        float4 x0 = __ldg(&src[cv0.x * CHUNKS + tx]);
        float4 x1 = __ldg(&src[cv1.x * CHUNKS + tx]);
        float v0 = __int_as_float(cv0.y);
        float v1 = __int_as_float(cv1.y);
        a.x = fmaf(v0, x0.x, a.x); a.y = fmaf(v0, x0.y, a.y);
        a.z = fmaf(v0, x0.z, a.z); a.w = fmaf(v0, x0.w, a.w);
        a.x = fmaf(v1, x1.x, a.x); a.y = fmaf(v1, x1.y, a.y);
        a.z = fmaf(v1, x1.z, a.z); a.w = fmaf(v1, x1.w, a.w);
    }
    if (e < end) {
        int2 cv = g_colval[e];
        float4 x = __ldg(&src[cv.x * CHUNKS + tx]);
        float v = __int_as_float(cv.y);
        a.x = fmaf(v, x.x, a.x); a.y = fmaf(v, x.y, a.y);
        a.z = fmaf(v, x.z, a.z); a.w = fmaf(v, x.w, a.w);
    }

    int idx = row * CHUNKS + tx;
    float4 eo = __ldg(&src[idx]);           // old ego (== X for mode 0)
    float4 en = make_float4(fmaf(a.x, eo.x, a.x),
                            fmaf(a.y, eo.y, a.y),
                            fmaf(a.z, eo.z, a.z),
                            fmaf(a.w, eo.w, a.w));
    if (mode != 2) dst[idx] = en;

    if (mode == 0) {
        acc[idx] = make_float4(eo.x + en.x, eo.y + en.y,
                               eo.z + en.z, eo.w + en.w);
    } else if (mode == 1) {
        float4 o = acc[idx];
        acc[idx] = make_float4(o.x + en.x, o.y + en.y,
                               o.z + en.z, o.w + en.w);
    } else {
        float4 o = acc[idx];
        acc[idx] = make_float4((o.x + en.x) * 0.25f, (o.y + en.y) * 0.25f,
                               (o.z + en.z) * 0.25f, (o.w + en.w) * 0.25f);
    }
}

extern "C" void kernel_launch(void* const* d_in, const int* in_sizes, int n_in,
                              void* d_out, int out_size) {
    const float4* X    = (const float4*)d_in[0];   // [N,96] f32
    const float*  vals = (const float*) d_in[1];   // [E]
    const void*   rows = d_in[2];                  // [E] i64 or i32
    const void*   cols = d_in[3];
    int E = in_sizes[1];
    float4* acc = (float4*)d_out;

    // dtype detect
    reset_flag_kernel<<<1, 1>>>();
    detect_i64_kernel<<<512, 256>>>((const unsigned int*)rows, E / 2);

    // CSR build
    zero_deg_kernel<<<(N_NODES + 255) / 256, 256>>>();
    hist_kernel<<<(E + 255) / 256, 256>>>(rows, E);
    scan_kernel<<<1, 1024>>>();
    scatter_kernel<<<(E + 255) / 256, 256>>>(vals, rows, cols, E);

    // fused layers (double-buffered ego)
    float4* egoA = nullptr; float4* egoB = nullptr;
    cudaGetSymbolAddress((void**)&egoA, g_egoA);
    cudaGetSymbolAddress((void**)&egoB, g_egoB);

    dim3 blk(CHUNKS, 8);                 // 192 threads, 8 rows per block
    int  grd = (N_NODES + 7) / 8;

    gnn_layer_kernel<<<grd, blk>>>(X,    egoA, acc, 0);
    gnn_layer_kernel<<<grd, blk>>>(egoA, egoB, acc, 1);
    gnn_layer_kernel<<<grd, blk>>>(egoB, egoA, acc, 2);
}